// round 2
// baseline (speedup 1.0000x reference)
#include <cuda_runtime.h>
#include <math.h>

// Problem constants
#define B_SZ   8
#define N_SEQ  1024
#define C_DIM  768
#define H_HEAD 12
#define D_HEAD 64
#define QKV_LD 2304            // 3*C
#define SCALE  0.125f          // 64^-0.5

// Scratch (allocation-free: __device__ globals)
__device__ float g_qkv[(size_t)B_SZ * N_SEQ * 3 * C_DIM];          // [8192, 2304]  (b,n, s*768+h*64+d)
__device__ float g_scores[(size_t)B_SZ * H_HEAD * N_SEQ * N_SEQ];  // [96, 1024, 1024]
__device__ float g_av[(size_t)B_SZ * N_SEQ * C_DIM];               // [8192, 768]   (b,n, h*64+d)

// ---------------------------------------------------------------------------
// Generic NN GEMM with bias: C[M,N] = A[M,K] @ B[K,N] + bias[N]
// 128x128 block, BK=16, 256 threads, 8x8 per thread. Dims must divide tiles.
// ---------------------------------------------------------------------------
__global__ __launch_bounds__(256) void gemm_nn_bias(
    const float* __restrict__ A, const float* __restrict__ B,
    const float* __restrict__ bias, float* __restrict__ C,
    int K, int lda, int ldb, int ldc)
{
    __shared__ float As[16][128];
    __shared__ float Bs[16][128];
    const int tid = threadIdx.x;
    const int tx = tid & 15, ty = tid >> 4;
    const int row0 = blockIdx.y * 128;
    const int col0 = blockIdx.x * 128;

    float acc[8][8];
#pragma unroll
    for (int i = 0; i < 8; i++)
#pragma unroll
        for (int j = 0; j < 8; j++) acc[i][j] = 0.f;

    for (int k0 = 0; k0 < K; k0 += 16) {
#pragma unroll
        for (int l = 0; l < 2; l++) {
            int f = tid + l * 256;
            int r = f >> 2;
            int cv = (f & 3) << 2;
            float4 v = *reinterpret_cast<const float4*>(A + (size_t)(row0 + r) * lda + k0 + cv);
            As[cv + 0][r] = v.x; As[cv + 1][r] = v.y; As[cv + 2][r] = v.z; As[cv + 3][r] = v.w;
        }
#pragma unroll
        for (int l = 0; l < 2; l++) {
            int f = tid + l * 256;
            int r = f >> 5;
            int cv = (f & 31) << 2;
            *reinterpret_cast<float4*>(&Bs[r][cv]) =
                *reinterpret_cast<const float4*>(B + (size_t)(k0 + r) * ldb + col0 + cv);
        }
        __syncthreads();
#pragma unroll
        for (int k = 0; k < 16; k++) {
            float4 a0 = *reinterpret_cast<const float4*>(&As[k][ty * 8]);
            float4 a1 = *reinterpret_cast<const float4*>(&As[k][ty * 8 + 4]);
            float4 b0 = *reinterpret_cast<const float4*>(&Bs[k][tx * 8]);
            float4 b1 = *reinterpret_cast<const float4*>(&Bs[k][tx * 8 + 4]);
            float a[8] = {a0.x, a0.y, a0.z, a0.w, a1.x, a1.y, a1.z, a1.w};
            float b[8] = {b0.x, b0.y, b0.z, b0.w, b1.x, b1.y, b1.z, b1.w};
#pragma unroll
            for (int i = 0; i < 8; i++)
#pragma unroll
                for (int j = 0; j < 8; j++) acc[i][j] = fmaf(a[i], b[j], acc[i][j]);
        }
        __syncthreads();
    }
#pragma unroll
    for (int i = 0; i < 8; i++) {
        int r = row0 + ty * 8 + i;
#pragma unroll
        for (int j = 0; j < 8; j++) {
            int c = col0 + tx * 8 + j;
            C[(size_t)r * ldc + c] = acc[i][j] + bias[c];
        }
    }
}

// ---------------------------------------------------------------------------
// QK^T: scores[z, n, m] = SCALE * sum_d q[z,n,d] * k[z,m,d], z = b*12+h
// q, k live strided inside g_qkv (lda = 2304). NT GEMM, K=64.
// ---------------------------------------------------------------------------
__global__ __launch_bounds__(256) void qk_kernel()
{
    const int z = blockIdx.z;
    const int b = z / H_HEAD, h = z % H_HEAD;
    const float* Aq = g_qkv + (size_t)b * N_SEQ * QKV_LD + h * D_HEAD;          // q
    const float* Bk = g_qkv + (size_t)b * N_SEQ * QKV_LD + C_DIM + h * D_HEAD;  // k
    float* C = g_scores + (size_t)z * N_SEQ * N_SEQ;

    __shared__ float As[16][128];
    __shared__ float Bs[16][128];
    const int tid = threadIdx.x;
    const int tx = tid & 15, ty = tid >> 4;
    const int row0 = blockIdx.y * 128;  // n
    const int col0 = blockIdx.x * 128;  // m

    float acc[8][8];
#pragma unroll
    for (int i = 0; i < 8; i++)
#pragma unroll
        for (int j = 0; j < 8; j++) acc[i][j] = 0.f;

#pragma unroll
    for (int k0 = 0; k0 < D_HEAD; k0 += 16) {
#pragma unroll
        for (int l = 0; l < 2; l++) {
            int f = tid + l * 256;
            int r = f >> 2;
            int cv = (f & 3) << 2;
            float4 v = *reinterpret_cast<const float4*>(Aq + (size_t)(row0 + r) * QKV_LD + k0 + cv);
            As[cv + 0][r] = v.x; As[cv + 1][r] = v.y; As[cv + 2][r] = v.z; As[cv + 3][r] = v.w;
            float4 w = *reinterpret_cast<const float4*>(Bk + (size_t)(col0 + r) * QKV_LD + k0 + cv);
            Bs[cv + 0][r] = w.x; Bs[cv + 1][r] = w.y; Bs[cv + 2][r] = w.z; Bs[cv + 3][r] = w.w;
        }
        __syncthreads();
#pragma unroll
        for (int k = 0; k < 16; k++) {
            float4 a0 = *reinterpret_cast<const float4*>(&As[k][ty * 8]);
            float4 a1 = *reinterpret_cast<const float4*>(&As[k][ty * 8 + 4]);
            float4 b0 = *reinterpret_cast<const float4*>(&Bs[k][tx * 8]);
            float4 b1 = *reinterpret_cast<const float4*>(&Bs[k][tx * 8 + 4]);
            float a[8] = {a0.x, a0.y, a0.z, a0.w, a1.x, a1.y, a1.z, a1.w};
            float b[8] = {b0.x, b0.y, b0.z, b0.w, b1.x, b1.y, b1.z, b1.w};
#pragma unroll
            for (int i = 0; i < 8; i++)
#pragma unroll
                for (int j = 0; j < 8; j++) acc[i][j] = fmaf(a[i], b[j], acc[i][j]);
        }
        __syncthreads();
    }
#pragma unroll
    for (int i = 0; i < 8; i++) {
        int r = row0 + ty * 8 + i;
#pragma unroll
        for (int j = 0; j < 8; j++) {
            C[(size_t)r * N_SEQ + col0 + tx * 8 + j] = acc[i][j] * SCALE;
        }
    }
}

// ---------------------------------------------------------------------------
// Fused pre-mix (w_l) -> softmax over m -> post-mix (w_w), in-place on scores.
// One CTA per (b, n); thread t owns columns m = 4t..4t+3 for all 12 heads.
// ---------------------------------------------------------------------------
__global__ __launch_bounds__(256) void mixsoftmax_kernel(
    const float* __restrict__ w_l, const float* __restrict__ b_l,
    const float* __restrict__ w_w, const float* __restrict__ b_w)
{
    __shared__ float swl[144], sww[144], sbl[12], sbw[12];
    __shared__ float red[8][12];
    const int tid = threadIdx.x;
    if (tid < 144) { swl[tid] = w_l[tid]; sww[tid] = w_w[tid]; }
    if (tid < 12)  { sbl[tid] = b_l[tid]; sbw[tid] = b_w[tid]; }
    __syncthreads();

    const int bn = blockIdx.x;
    const int b = bn >> 10, n = bn & 1023;
    const size_t base = ((size_t)b * H_HEAD * N_SEQ + n) * N_SEQ;  // + h * N_SEQ*N_SEQ
    const int m0 = tid * 4;
    const int lane = tid & 31, wid = tid >> 5;

    // pre-mix: t[g][c] = b_l[g] + sum_h s[h][m] * w_l[h,g]
    float t[12][4];
#pragma unroll
    for (int g = 0; g < 12; g++) {
        float bl = sbl[g];
        t[g][0] = bl; t[g][1] = bl; t[g][2] = bl; t[g][3] = bl;
    }
#pragma unroll
    for (int h = 0; h < 12; h++) {
        float4 s4 = *reinterpret_cast<const float4*>(g_scores + base + (size_t)h * N_SEQ * N_SEQ + m0);
#pragma unroll
        for (int g = 0; g < 12; g++) {
            float wl = swl[h * 12 + g];
            t[g][0] = fmaf(s4.x, wl, t[g][0]);
            t[g][1] = fmaf(s4.y, wl, t[g][1]);
            t[g][2] = fmaf(s4.z, wl, t[g][2]);
            t[g][3] = fmaf(s4.w, wl, t[g][3]);
        }
    }

    // row max per g (block reduce over 1024 columns)
    float lmax[12];
#pragma unroll
    for (int g = 0; g < 12; g++) {
        float v = fmaxf(fmaxf(t[g][0], t[g][1]), fmaxf(t[g][2], t[g][3]));
#pragma unroll
        for (int o = 16; o > 0; o >>= 1) v = fmaxf(v, __shfl_xor_sync(0xffffffffu, v, o));
        if (lane == 0) red[wid][g] = v;
    }
    __syncthreads();
#pragma unroll
    for (int g = 0; g < 12; g++) {
        float v = red[0][g];
#pragma unroll
        for (int w = 1; w < 8; w++) v = fmaxf(v, red[w][g]);
        lmax[g] = v;
    }
    __syncthreads();

    // exp + row sum
    float lsum[12];
#pragma unroll
    for (int g = 0; g < 12; g++) {
        t[g][0] = __expf(t[g][0] - lmax[g]);
        t[g][1] = __expf(t[g][1] - lmax[g]);
        t[g][2] = __expf(t[g][2] - lmax[g]);
        t[g][3] = __expf(t[g][3] - lmax[g]);
        float v = (t[g][0] + t[g][1]) + (t[g][2] + t[g][3]);
#pragma unroll
        for (int o = 16; o > 0; o >>= 1) v += __shfl_xor_sync(0xffffffffu, v, o);
        if (lane == 0) red[wid][g] = v;
    }
    __syncthreads();
#pragma unroll
    for (int g = 0; g < 12; g++) {
        float v = red[0][g];
#pragma unroll
        for (int w = 1; w < 8; w++) v += red[w][g];
        lsum[g] = 1.0f / v;
    }

    // normalize
#pragma unroll
    for (int g = 0; g < 12; g++) {
        t[g][0] *= lsum[g]; t[g][1] *= lsum[g]; t[g][2] *= lsum[g]; t[g][3] *= lsum[g];
    }

    // post-mix + in-place write (thread only touches its own columns: safe)
#pragma unroll
    for (int g = 0; g < 12; g++) {
        float o0 = sbw[g], o1 = sbw[g], o2 = sbw[g], o3 = sbw[g];
#pragma unroll
        for (int h = 0; h < 12; h++) {
            float ww = sww[h * 12 + g];
            o0 = fmaf(t[h][0], ww, o0);
            o1 = fmaf(t[h][1], ww, o1);
            o2 = fmaf(t[h][2], ww, o2);
            o3 = fmaf(t[h][3], ww, o3);
        }
        float4 out4 = make_float4(o0, o1, o2, o3);
        *reinterpret_cast<float4*>(g_scores + base + (size_t)g * N_SEQ * N_SEQ + m0) = out4;
    }
}

// ---------------------------------------------------------------------------
// AV: av[b, n, h*64+d] = sum_m attn[z, n, m] * v[z, m, d], z = b*12+h
// 128x64 block, BK=16, 256 threads, 8x4 per thread. K=1024.
// ---------------------------------------------------------------------------
__global__ __launch_bounds__(256) void av_kernel()
{
    const int z = blockIdx.z;
    const int b = z / H_HEAD, h = z % H_HEAD;
    const float* A  = g_scores + (size_t)z * N_SEQ * N_SEQ;
    const float* Bv = g_qkv + (size_t)b * N_SEQ * QKV_LD + 2 * C_DIM + h * D_HEAD;
    float* C = g_av + (size_t)b * N_SEQ * C_DIM + h * D_HEAD;

    __shared__ float As[16][128];
    __shared__ float Bs[16][64];
    const int tid = threadIdx.x;
    const int tx = tid & 15, ty = tid >> 4;
    const int row0 = blockIdx.y * 128;

    float acc[8][4];
#pragma unroll
    for (int i = 0; i < 8; i++)
#pragma unroll
        for (int j = 0; j < 4; j++) acc[i][j] = 0.f;

    for (int k0 = 0; k0 < N_SEQ; k0 += 16) {
#pragma unroll
        for (int l = 0; l < 2; l++) {
            int f = tid + l * 256;
            int r = f >> 2;
            int cv = (f & 3) << 2;
            float4 v = *reinterpret_cast<const float4*>(A + (size_t)(row0 + r) * N_SEQ + k0 + cv);
            As[cv + 0][r] = v.x; As[cv + 1][r] = v.y; As[cv + 2][r] = v.z; As[cv + 3][r] = v.w;
        }
        {
            int r = tid >> 4;
            int cv = (tid & 15) << 2;
            *reinterpret_cast<float4*>(&Bs[r][cv]) =
                *reinterpret_cast<const float4*>(Bv + (size_t)(k0 + r) * QKV_LD + cv);
        }
        __syncthreads();
#pragma unroll
        for (int k = 0; k < 16; k++) {
            float4 a0 = *reinterpret_cast<const float4*>(&As[k][ty * 8]);
            float4 a1 = *reinterpret_cast<const float4*>(&As[k][ty * 8 + 4]);
            float4 bq = *reinterpret_cast<const float4*>(&Bs[k][tx * 4]);
            float a[8] = {a0.x, a0.y, a0.z, a0.w, a1.x, a1.y, a1.z, a1.w};
            float bb[4] = {bq.x, bq.y, bq.z, bq.w};
#pragma unroll
            for (int i = 0; i < 8; i++)
#pragma unroll
                for (int j = 0; j < 4; j++) acc[i][j] = fmaf(a[i], bb[j], acc[i][j]);
        }
        __syncthreads();
    }
#pragma unroll
    for (int i = 0; i < 8; i++) {
        int r = row0 + ty * 8 + i;
#pragma unroll
        for (int j = 0; j < 4; j++) {
            C[(size_t)r * C_DIM + tx * 4 + j] = acc[i][j];
        }
    }
}

// ---------------------------------------------------------------------------
extern "C" void kernel_launch(void* const* d_in, const int* in_sizes, int n_in,
                              void* d_out, int out_size)
{
    const float* x      = (const float*)d_in[0];
    const float* w_qkv  = (const float*)d_in[1];
    const float* b_qkv  = (const float*)d_in[2];
    const float* w_l    = (const float*)d_in[3];
    const float* b_l    = (const float*)d_in[4];
    const float* w_w    = (const float*)d_in[5];
    const float* b_w    = (const float*)d_in[6];
    const float* w_proj = (const float*)d_in[7];
    const float* b_proj = (const float*)d_in[8];
    float* out = (float*)d_out;

    float *qkv_p = nullptr, *av_p = nullptr;
    cudaGetSymbolAddress((void**)&qkv_p, g_qkv);
    cudaGetSymbolAddress((void**)&av_p, g_av);

    dim3 blk(256);

    // 1) QKV projection: [8192,768] @ [768,2304] + bias
    gemm_nn_bias<<<dim3(3 * C_DIM / 128, B_SZ * N_SEQ / 128), blk>>>(
        x, w_qkv, b_qkv, qkv_p, C_DIM, C_DIM, QKV_LD, QKV_LD);

    // 2) scores = SCALE * q @ k^T per (b,h)
    qk_kernel<<<dim3(N_SEQ / 128, N_SEQ / 128, B_SZ * H_HEAD), blk>>>();

    // 3) fused talking-heads pre-mix + softmax + post-mix (in place)
    mixsoftmax_kernel<<<B_SZ * N_SEQ, 256>>>(w_l, b_l, w_w, b_w);

    // 4) av = attn @ v, written as [b, n, h*64+d]
    av_kernel<<<dim3(1, N_SEQ / 128, B_SZ * H_HEAD), blk>>>();

    // 5) out = av @ w_proj + b_proj
    gemm_nn_bias<<<dim3(C_DIM / 128, B_SZ * N_SEQ / 128), blk>>>(
        av_p, w_proj, b_proj, out, C_DIM, C_DIM, C_DIM, C_DIM);
}

// round 3
// speedup vs baseline: 2.0999x; 2.0999x over previous
#include <cuda_runtime.h>
#include <math.h>

// Problem constants
#define B_SZ   8
#define N_SEQ  1024
#define C_DIM  768
#define H_HEAD 12
#define D_HEAD 64
#define QKV_LD 2304            // 3*C
#define SCALE  0.125f          // 64^-0.5

// Scratch (allocation-free: __device__ globals)
__device__ float g_qkv[(size_t)B_SZ * N_SEQ * 3 * C_DIM];          // [8192, 2304]
__device__ float g_scores[(size_t)B_SZ * H_HEAD * N_SEQ * N_SEQ];  // [96, 1024, 1024]
__device__ float g_av[(size_t)B_SZ * N_SEQ * C_DIM];               // [8192, 768]
__device__ float g_vT[(size_t)B_SZ * H_HEAD * D_HEAD * N_SEQ];     // [96, 64, 1024]
__device__ float g_wqkvT[(size_t)3 * C_DIM * C_DIM];               // [2304, 768]
__device__ float g_wprojT[(size_t)C_DIM * C_DIM];                  // [768, 768]

// ---------------------------------------------------------------------------
// helpers
// ---------------------------------------------------------------------------
__device__ __forceinline__ unsigned f2tf(float x) {
    unsigned u;
    asm("cvt.rna.tf32.f32 %0, %1;" : "=r"(u) : "f"(x));
    return u;
}

#define MMA_TF32(d, a, b)                                                     \
    asm volatile(                                                             \
        "mma.sync.aligned.m16n8k8.row.col.f32.tf32.tf32.f32 "                 \
        "{%0,%1,%2,%3}, {%4,%5,%6,%7}, {%8,%9}, {%0,%1,%2,%3};"               \
        : "+f"(d[0]), "+f"(d[1]), "+f"(d[2]), "+f"(d[3])                      \
        : "r"(a[0]), "r"(a[1]), "r"(a[2]), "r"(a[3]), "r"(b[0]), "r"(b[1]))

// ---------------------------------------------------------------------------
// Generic NT tf32 tensor GEMM: C[M,N] = scale * (A[M,K] @ B[N,K]^T) + bias[N]
// BM=128, BK=16, 256 threads (8 warps in 4x2), warp tile 32 x (BN/2),
// mma m16n8k8. Batched over blockIdx.z with split strides (z/12, z%12).
// All dims must divide tiles (they do for this problem).
// ---------------------------------------------------------------------------
template<int BN>
__global__ __launch_bounds__(256) void gemm_nt_tf32(
    const float* __restrict__ Ag, const float* __restrict__ Bg,
    const float* __restrict__ bias, float* __restrict__ Cg,
    int K, int lda, int ldb, int ldc,
    long long az1, long long az2, long long bz1, long long bz2,
    long long cz1, long long cz2, float scale)
{
    constexpr int WN = BN / 2;    // warp N tile
    constexpr int NI = WN / 8;    // mma tiles along N per warp
    constexpr int BLD = BN / 64;  // B-tile float4 load rounds

    __shared__ unsigned As[128][20];
    __shared__ unsigned Bs[BN][20];

    const int tid = threadIdx.x;
    const int lane = tid & 31, warp = tid >> 5;
    const int wm = warp & 3, wn = warp >> 2;
    const int g = lane >> 2, tg = lane & 3;

    const int z = blockIdx.z;
    const int zb = z / H_HEAD, zh = z % H_HEAD;
    const float* A = Ag + zb * az1 + zh * az2 + (size_t)blockIdx.y * 128 * lda;
    const float* B = Bg + zb * bz1 + zh * bz2 + (size_t)blockIdx.x * BN * ldb;
    float* C = Cg + zb * cz1 + zh * cz2;

    float acc[2][NI][4];
#pragma unroll
    for (int mi = 0; mi < 2; mi++)
#pragma unroll
        for (int ni = 0; ni < NI; ni++)
#pragma unroll
            for (int j = 0; j < 4; j++) acc[mi][ni][j] = 0.f;

    for (int k0 = 0; k0 < K; k0 += 16) {
        // A tile: 128x16 -> 512 float4, 2 per thread
#pragma unroll
        for (int l = 0; l < 2; l++) {
            int f = tid + l * 256;
            int r = f >> 2, kc = (f & 3) << 2;
            float4 v = *reinterpret_cast<const float4*>(A + (size_t)r * lda + k0 + kc);
            uint4 u = make_uint4(f2tf(v.x), f2tf(v.y), f2tf(v.z), f2tf(v.w));
            *reinterpret_cast<uint4*>(&As[r][kc]) = u;
        }
        // B tile: BNx16
#pragma unroll
        for (int l = 0; l < BLD; l++) {
            int f = tid + l * 256;
            int r = f >> 2, kc = (f & 3) << 2;
            float4 v = *reinterpret_cast<const float4*>(B + (size_t)r * ldb + k0 + kc);
            uint4 u = make_uint4(f2tf(v.x), f2tf(v.y), f2tf(v.z), f2tf(v.w));
            *reinterpret_cast<uint4*>(&Bs[r][kc]) = u;
        }
        __syncthreads();

#pragma unroll
        for (int kk = 0; kk < 16; kk += 8) {
            unsigned a[2][4], b[NI][2];
#pragma unroll
            for (int mi = 0; mi < 2; mi++) {
                int r = wm * 32 + mi * 16 + g;
                a[mi][0] = As[r][kk + tg];
                a[mi][1] = As[r + 8][kk + tg];
                a[mi][2] = As[r][kk + 4 + tg];
                a[mi][3] = As[r + 8][kk + 4 + tg];
            }
#pragma unroll
            for (int ni = 0; ni < NI; ni++) {
                int n = wn * WN + ni * 8 + g;
                b[ni][0] = Bs[n][kk + tg];
                b[ni][1] = Bs[n][kk + 4 + tg];
            }
#pragma unroll
            for (int mi = 0; mi < 2; mi++)
#pragma unroll
                for (int ni = 0; ni < NI; ni++)
                    MMA_TF32(acc[mi][ni], a[mi], b[ni]);
        }
        __syncthreads();
    }

    // epilogue
    const int row_base = blockIdx.y * 128 + wm * 32;
    const int col_base = blockIdx.x * BN + wn * WN;
#pragma unroll
    for (int mi = 0; mi < 2; mi++) {
#pragma unroll
        for (int ni = 0; ni < NI; ni++) {
            int r0 = row_base + mi * 16 + g;
            int c = col_base + ni * 8 + 2 * tg;
            float b0 = 0.f, b1 = 0.f;
            if (bias) { b0 = bias[c]; b1 = bias[c + 1]; }
            float2 v0 = make_float2(acc[mi][ni][0] * scale + b0,
                                    acc[mi][ni][1] * scale + b1);
            float2 v1 = make_float2(acc[mi][ni][2] * scale + b0,
                                    acc[mi][ni][3] * scale + b1);
            *reinterpret_cast<float2*>(C + (size_t)r0 * ldc + c) = v0;
            *reinterpret_cast<float2*>(C + (size_t)(r0 + 8) * ldc + c) = v1;
        }
    }
}

// ---------------------------------------------------------------------------
// 32x32 tiled transpose: out[c][r] = in[r][c].  R, C divisible by 32.
// block (32,8)
// ---------------------------------------------------------------------------
__global__ void transpose2d(const float* __restrict__ in, float* __restrict__ out,
                            int R, int Cc)
{
    __shared__ float t[32][33];
    int c0 = blockIdx.x * 32, r0 = blockIdx.y * 32;
    int x = threadIdx.x, y = threadIdx.y;
#pragma unroll
    for (int i = 0; i < 4; i++)
        t[y + i * 8][x] = in[(size_t)(r0 + y + i * 8) * Cc + c0 + x];
    __syncthreads();
#pragma unroll
    for (int i = 0; i < 4; i++)
        out[(size_t)(c0 + y + i * 8) * R + r0 + x] = t[x][y + i * 8];
}

// V slice of g_qkv -> g_vT[z][d][m].  grid (32, 2, 96), block (32,8)
__global__ void transpose_v()
{
    __shared__ float t[32][33];
    int z = blockIdx.z;
    int b = z / H_HEAD, h = z % H_HEAD;
    const float* in = g_qkv + (size_t)b * N_SEQ * QKV_LD + 2 * C_DIM + h * D_HEAD;
    float* out = g_vT + (size_t)z * D_HEAD * N_SEQ;
    int m0 = blockIdx.x * 32, d0 = blockIdx.y * 32;
    int x = threadIdx.x, y = threadIdx.y;
#pragma unroll
    for (int i = 0; i < 4; i++)
        t[y + i * 8][x] = in[(size_t)(m0 + y + i * 8) * QKV_LD + d0 + x];
    __syncthreads();
#pragma unroll
    for (int i = 0; i < 4; i++)
        out[(size_t)(d0 + y + i * 8) * N_SEQ + m0 + x] = t[x][y + i * 8];
}

// ---------------------------------------------------------------------------
// Fused pre-mix (w_l) -> softmax over m -> post-mix (w_w), in-place on scores.
// One CTA per (b, n); thread t owns columns m = 4t..4t+3 for all 12 heads.
// ---------------------------------------------------------------------------
__global__ __launch_bounds__(256) void mixsoftmax_kernel(
    const float* __restrict__ w_l, const float* __restrict__ b_l,
    const float* __restrict__ w_w, const float* __restrict__ b_w)
{
    __shared__ float swl[144], sww[144], sbl[12], sbw[12];
    __shared__ float red[8][12];
    const int tid = threadIdx.x;
    if (tid < 144) { swl[tid] = w_l[tid]; sww[tid] = w_w[tid]; }
    if (tid < 12)  { sbl[tid] = b_l[tid]; sbw[tid] = b_w[tid]; }
    __syncthreads();

    const int bn = blockIdx.x;
    const int b = bn >> 10, n = bn & 1023;
    const size_t base = ((size_t)b * H_HEAD * N_SEQ + n) * N_SEQ;
    const int m0 = tid * 4;
    const int lane = tid & 31, wid = tid >> 5;

    float t[12][4];
#pragma unroll
    for (int g = 0; g < 12; g++) {
        float bl = sbl[g];
        t[g][0] = bl; t[g][1] = bl; t[g][2] = bl; t[g][3] = bl;
    }
#pragma unroll
    for (int h = 0; h < 12; h++) {
        float4 s4 = *reinterpret_cast<const float4*>(g_scores + base + (size_t)h * N_SEQ * N_SEQ + m0);
#pragma unroll
        for (int g = 0; g < 12; g++) {
            float wl = swl[h * 12 + g];
            t[g][0] = fmaf(s4.x, wl, t[g][0]);
            t[g][1] = fmaf(s4.y, wl, t[g][1]);
            t[g][2] = fmaf(s4.z, wl, t[g][2]);
            t[g][3] = fmaf(s4.w, wl, t[g][3]);
        }
    }

    float lmax[12];
#pragma unroll
    for (int g = 0; g < 12; g++) {
        float v = fmaxf(fmaxf(t[g][0], t[g][1]), fmaxf(t[g][2], t[g][3]));
#pragma unroll
        for (int o = 16; o > 0; o >>= 1) v = fmaxf(v, __shfl_xor_sync(0xffffffffu, v, o));
        if (lane == 0) red[wid][g] = v;
    }
    __syncthreads();
#pragma unroll
    for (int g = 0; g < 12; g++) {
        float v = red[0][g];
#pragma unroll
        for (int w = 1; w < 8; w++) v = fmaxf(v, red[w][g]);
        lmax[g] = v;
    }
    __syncthreads();

    float lsum[12];
#pragma unroll
    for (int g = 0; g < 12; g++) {
        t[g][0] = __expf(t[g][0] - lmax[g]);
        t[g][1] = __expf(t[g][1] - lmax[g]);
        t[g][2] = __expf(t[g][2] - lmax[g]);
        t[g][3] = __expf(t[g][3] - lmax[g]);
        float v = (t[g][0] + t[g][1]) + (t[g][2] + t[g][3]);
#pragma unroll
        for (int o = 16; o > 0; o >>= 1) v += __shfl_xor_sync(0xffffffffu, v, o);
        if (lane == 0) red[wid][g] = v;
    }
    __syncthreads();
#pragma unroll
    for (int g = 0; g < 12; g++) {
        float v = red[0][g];
#pragma unroll
        for (int w = 1; w < 8; w++) v += red[w][g];
        lsum[g] = 1.0f / v;
    }

#pragma unroll
    for (int g = 0; g < 12; g++) {
        t[g][0] *= lsum[g]; t[g][1] *= lsum[g]; t[g][2] *= lsum[g]; t[g][3] *= lsum[g];
    }

#pragma unroll
    for (int g = 0; g < 12; g++) {
        float o0 = sbw[g], o1 = sbw[g], o2 = sbw[g], o3 = sbw[g];
#pragma unroll
        for (int h = 0; h < 12; h++) {
            float ww = sww[h * 12 + g];
            o0 = fmaf(t[h][0], ww, o0);
            o1 = fmaf(t[h][1], ww, o1);
            o2 = fmaf(t[h][2], ww, o2);
            o3 = fmaf(t[h][3], ww, o3);
        }
        *reinterpret_cast<float4*>(g_scores + base + (size_t)g * N_SEQ * N_SEQ + m0) =
            make_float4(o0, o1, o2, o3);
    }
}

// ---------------------------------------------------------------------------
extern "C" void kernel_launch(void* const* d_in, const int* in_sizes, int n_in,
                              void* d_out, int out_size)
{
    const float* x      = (const float*)d_in[0];
    const float* w_qkv  = (const float*)d_in[1];
    const float* b_qkv  = (const float*)d_in[2];
    const float* w_l    = (const float*)d_in[3];
    const float* b_l    = (const float*)d_in[4];
    const float* w_w    = (const float*)d_in[5];
    const float* b_w    = (const float*)d_in[6];
    const float* w_proj = (const float*)d_in[7];
    const float* b_proj = (const float*)d_in[8];
    float* out = (float*)d_out;

    float *qkv_p, *scores_p, *av_p, *vT_p, *wqkvT_p, *wprojT_p;
    cudaGetSymbolAddress((void**)&qkv_p, g_qkv);
    cudaGetSymbolAddress((void**)&scores_p, g_scores);
    cudaGetSymbolAddress((void**)&av_p, g_av);
    cudaGetSymbolAddress((void**)&vT_p, g_vT);
    cudaGetSymbolAddress((void**)&wqkvT_p, g_wqkvT);
    cudaGetSymbolAddress((void**)&wprojT_p, g_wprojT);

    // 0) weight transposes (cheap; keeps every GEMM in the NT form)
    transpose2d<<<dim3(QKV_LD / 32, C_DIM / 32), dim3(32, 8)>>>(w_qkv, wqkvT_p, C_DIM, QKV_LD);
    transpose2d<<<dim3(C_DIM / 32, C_DIM / 32), dim3(32, 8)>>>(w_proj, wprojT_p, C_DIM, C_DIM);

    const long long QB = (long long)N_SEQ * QKV_LD;      // per-b stride in g_qkv
    const long long SH = (long long)N_SEQ * N_SEQ;       // per-h stride in scores
    const long long VH = (long long)D_HEAD * N_SEQ;      // per-h stride in g_vT

    // 1) QKV projection: [8192,768] @ wqkvT[2304,768]^T + bias
    gemm_nt_tf32<128><<<dim3(QKV_LD / 128, B_SZ * N_SEQ / 128, 1), 256>>>(
        x, wqkvT_p, b_qkv, qkv_p, C_DIM, C_DIM, C_DIM, QKV_LD,
        0, 0, 0, 0, 0, 0, 1.0f);

    // 2) transpose V slices into g_vT[z][d][m]
    transpose_v<<<dim3(N_SEQ / 32, D_HEAD / 32, B_SZ * H_HEAD), dim3(32, 8)>>>();

    // 3) scores = SCALE * q @ k^T per (b,h)
    gemm_nt_tf32<128><<<dim3(N_SEQ / 128, N_SEQ / 128, B_SZ * H_HEAD), 256>>>(
        qkv_p, qkv_p + C_DIM, nullptr, scores_p, D_HEAD, QKV_LD, QKV_LD, N_SEQ,
        QB, D_HEAD, QB, D_HEAD, H_HEAD * SH, SH, SCALE);

    // 4) fused talking-heads pre-mix + softmax + post-mix (in place)
    mixsoftmax_kernel<<<B_SZ * N_SEQ, 256>>>(w_l, b_l, w_w, b_w);

    // 5) av = attn @ vT^T  -> g_av[b][n][h*64+d]
    gemm_nt_tf32<64><<<dim3(1, N_SEQ / 128, B_SZ * H_HEAD), 256>>>(
        scores_p, vT_p, nullptr, av_p, N_SEQ, N_SEQ, N_SEQ, C_DIM,
        H_HEAD * SH, SH, H_HEAD * VH, VH, (long long)N_SEQ * C_DIM, D_HEAD, 1.0f);

    // 6) out = av @ wprojT^T + bias
    gemm_nt_tf32<128><<<dim3(C_DIM / 128, B_SZ * N_SEQ / 128, 1), 256>>>(
        av_p, wprojT_p, b_proj, out, C_DIM, C_DIM, C_DIM, C_DIM,
        0, 0, 0, 0, 0, 0, 1.0f);
}

// round 4
// speedup vs baseline: 2.4308x; 1.1576x over previous
#include <cuda_runtime.h>
#include <math.h>

// Problem constants
#define B_SZ   8
#define N_SEQ  1024
#define C_DIM  768
#define H_HEAD 12
#define D_HEAD 64
#define QKV_LD 2304            // 3*C
#define SCALE  0.125f          // 64^-0.5

// Scratch (allocation-free: __device__ globals)
__device__ float g_qkv[(size_t)B_SZ * N_SEQ * 3 * C_DIM];          // [8192, 2304]
__device__ float g_scores[(size_t)B_SZ * H_HEAD * N_SEQ * N_SEQ];  // [96, 1024, 1024]
__device__ float g_av[(size_t)B_SZ * N_SEQ * C_DIM];               // [8192, 768]
__device__ float g_vT[(size_t)B_SZ * H_HEAD * D_HEAD * N_SEQ];     // [96, 64, 1024] (tf32-rounded)
__device__ float g_wqkvT[(size_t)3 * C_DIM * C_DIM];               // [2304, 768]    (tf32-rounded)
__device__ float g_wprojT[(size_t)C_DIM * C_DIM];                  // [768, 768]     (tf32-rounded)

// ---------------------------------------------------------------------------
// helpers
// ---------------------------------------------------------------------------
__device__ __forceinline__ unsigned f2tf(float x) {
    unsigned u;
    asm("cvt.rna.tf32.f32 %0, %1;" : "=r"(u) : "f"(x));
    return u;
}

__device__ __forceinline__ void cpa16(unsigned s, const float* g) {
    asm volatile("cp.async.cg.shared.global [%0], [%1], 16;" :: "r"(s), "l"(g));
}
#define CPA_COMMIT() asm volatile("cp.async.commit_group;")
#define CPA_WAIT(n)  asm volatile("cp.async.wait_group %0;" :: "n"(n))

#define MMA_TF32(d, a, b)                                                     \
    asm volatile(                                                             \
        "mma.sync.aligned.m16n8k8.row.col.f32.tf32.tf32.f32 "                 \
        "{%0,%1,%2,%3}, {%4,%5,%6,%7}, {%8,%9}, {%0,%1,%2,%3};"               \
        : "+f"(d[0]), "+f"(d[1]), "+f"(d[2]), "+f"(d[3])                      \
        : "r"(a[0]), "r"(a[1]), "r"(a[2]), "r"(a[3]), "r"(b[0]), "r"(b[1]))

// ---------------------------------------------------------------------------
// Generic NT tf32 tensor GEMM: C[M,N] = scale * (A[M,K] @ B[N,K]^T) + bias[N]
// BM=128, BK=16, 256 threads (8 warps in 4x2), warp tile 32 x (BN/2),
// mma m16n8k8, 2-stage cp.async double buffering.
// A is always cvt'd at consume; B cvt'd at consume iff CVB (else pre-rounded).
// ---------------------------------------------------------------------------
template<int BN, bool CVB>
__global__ __launch_bounds__(256) void gemm_nt_tf32(
    const float* __restrict__ Ag, const float* __restrict__ Bg,
    const float* __restrict__ bias, float* __restrict__ Cg,
    int K, int lda, int ldb, int ldc,
    long long az1, long long az2, long long bz1, long long bz2,
    long long cz1, long long cz2, float scale)
{
    constexpr int WN = BN / 2;    // warp N tile
    constexpr int NI = WN / 8;    // mma tiles along N per warp
    constexpr int BLD = BN / 64;  // B-tile float4 load rounds

    __shared__ float As[2][128][20];
    __shared__ float Bs[2][BN][20];

    const int tid = threadIdx.x;
    const int lane = tid & 31, warp = tid >> 5;
    const int wm = warp & 3, wn = warp >> 2;
    const int g = lane >> 2, tg = lane & 3;

    const int z = blockIdx.z;
    const int zb = z / H_HEAD, zh = z % H_HEAD;
    const float* A = Ag + zb * az1 + zh * az2 + (size_t)blockIdx.y * 128 * lda;
    const float* B = Bg + zb * bz1 + zh * bz2 + (size_t)blockIdx.x * BN * ldb;
    float* C = Cg + zb * cz1 + zh * cz2;

    // per-thread load coords
    const int ar = tid >> 2;               // A row for l=0 (l=1 adds 64)
    const int akc = (tid & 3) << 2;        // k offset
    const int br = tid >> 2;
    const int bkc = (tid & 3) << 2;

    float acc[2][NI][4];
#pragma unroll
    for (int mi = 0; mi < 2; mi++)
#pragma unroll
        for (int ni = 0; ni < NI; ni++)
#pragma unroll
            for (int j = 0; j < 4; j++) acc[mi][ni][j] = 0.f;

    const int niter = K >> 4;

    auto stage_load = [&](int st, int k0) {
#pragma unroll
        for (int l = 0; l < 2; l++) {
            int r = ar + l * 64;
            unsigned sa = (unsigned)__cvta_generic_to_shared(&As[st][r][akc]);
            cpa16(sa, A + (size_t)r * lda + k0 + akc);
        }
#pragma unroll
        for (int l = 0; l < BLD; l++) {
            int r = br + l * 64;
            unsigned sb = (unsigned)__cvta_generic_to_shared(&Bs[st][r][bkc]);
            cpa16(sb, B + (size_t)r * ldb + k0 + bkc);
        }
        CPA_COMMIT();
    };

    stage_load(0, 0);

    for (int i = 0; i < niter; i++) {
        const int st = i & 1;
        if (i + 1 < niter) {
            stage_load(st ^ 1, (i + 1) << 4);
            CPA_WAIT(1);
        } else {
            CPA_WAIT(0);
        }
        __syncthreads();

#pragma unroll
        for (int kk = 0; kk < 16; kk += 8) {
            unsigned a[2][4], b[NI][2];
#pragma unroll
            for (int mi = 0; mi < 2; mi++) {
                int r = wm * 32 + mi * 16 + g;
                a[mi][0] = f2tf(As[st][r][kk + tg]);
                a[mi][1] = f2tf(As[st][r + 8][kk + tg]);
                a[mi][2] = f2tf(As[st][r][kk + 4 + tg]);
                a[mi][3] = f2tf(As[st][r + 8][kk + 4 + tg]);
            }
#pragma unroll
            for (int ni = 0; ni < NI; ni++) {
                int n = wn * WN + ni * 8 + g;
                if (CVB) {
                    b[ni][0] = f2tf(Bs[st][n][kk + tg]);
                    b[ni][1] = f2tf(Bs[st][n][kk + 4 + tg]);
                } else {
                    b[ni][0] = __float_as_uint(Bs[st][n][kk + tg]);
                    b[ni][1] = __float_as_uint(Bs[st][n][kk + 4 + tg]);
                }
            }
#pragma unroll
            for (int mi = 0; mi < 2; mi++)
#pragma unroll
                for (int ni = 0; ni < NI; ni++)
                    MMA_TF32(acc[mi][ni], a[mi], b[ni]);
        }
        __syncthreads();
    }

    // epilogue
    const int row_base = blockIdx.y * 128 + wm * 32;
    const int col_base = blockIdx.x * BN + wn * WN;
#pragma unroll
    for (int mi = 0; mi < 2; mi++) {
#pragma unroll
        for (int ni = 0; ni < NI; ni++) {
            int r0 = row_base + mi * 16 + g;
            int c = col_base + ni * 8 + 2 * tg;
            float b0 = 0.f, b1 = 0.f;
            if (bias) { b0 = bias[c]; b1 = bias[c + 1]; }
            float2 v0 = make_float2(acc[mi][ni][0] * scale + b0,
                                    acc[mi][ni][1] * scale + b1);
            float2 v1 = make_float2(acc[mi][ni][2] * scale + b0,
                                    acc[mi][ni][3] * scale + b1);
            *reinterpret_cast<float2*>(C + (size_t)r0 * ldc + c) = v0;
            *reinterpret_cast<float2*>(C + (size_t)(r0 + 8) * ldc + c) = v1;
        }
    }
}

// ---------------------------------------------------------------------------
// 32x32 tiled transpose + tf32 pre-round: out[c][r] = tf32(in[r][c])
// ---------------------------------------------------------------------------
__global__ void transpose2d(const float* __restrict__ in, float* __restrict__ out,
                            int R, int Cc)
{
    __shared__ float t[32][33];
    int c0 = blockIdx.x * 32, r0 = blockIdx.y * 32;
    int x = threadIdx.x, y = threadIdx.y;
#pragma unroll
    for (int i = 0; i < 4; i++)
        t[y + i * 8][x] = in[(size_t)(r0 + y + i * 8) * Cc + c0 + x];
    __syncthreads();
#pragma unroll
    for (int i = 0; i < 4; i++)
        out[(size_t)(c0 + y + i * 8) * R + r0 + x] =
            __uint_as_float(f2tf(t[x][y + i * 8]));
}

// V slice of g_qkv -> g_vT[z][d][m], tf32 pre-rounded.
__global__ void transpose_v()
{
    __shared__ float t[32][33];
    int z = blockIdx.z;
    int b = z / H_HEAD, h = z % H_HEAD;
    const float* in = g_qkv + (size_t)b * N_SEQ * QKV_LD + 2 * C_DIM + h * D_HEAD;
    float* out = g_vT + (size_t)z * D_HEAD * N_SEQ;
    int m0 = blockIdx.x * 32, d0 = blockIdx.y * 32;
    int x = threadIdx.x, y = threadIdx.y;
#pragma unroll
    for (int i = 0; i < 4; i++)
        t[y + i * 8][x] = in[(size_t)(m0 + y + i * 8) * QKV_LD + d0 + x];
    __syncthreads();
#pragma unroll
    for (int i = 0; i < 4; i++)
        out[(size_t)(d0 + y + i * 8) * N_SEQ + m0 + x] =
            __uint_as_float(f2tf(t[x][y + i * 8]));
}

// ---------------------------------------------------------------------------
// Fused pre-mix (w_l) -> softmax over m -> post-mix (w_w), in-place on scores.
// One CTA per (b, n); thread t owns columns m = 4t..4t+3 for all 12 heads.
// ---------------------------------------------------------------------------
__global__ __launch_bounds__(256) void mixsoftmax_kernel(
    const float* __restrict__ w_l, const float* __restrict__ b_l,
    const float* __restrict__ w_w, const float* __restrict__ b_w)
{
    __shared__ float swl[144], sww[144], sbl[12], sbw[12];
    __shared__ float red[8][12];
    const int tid = threadIdx.x;
    if (tid < 144) { swl[tid] = w_l[tid]; sww[tid] = w_w[tid]; }
    if (tid < 12)  { sbl[tid] = b_l[tid]; sbw[tid] = b_w[tid]; }
    __syncthreads();

    const int bn = blockIdx.x;
    const int b = bn >> 10, n = bn & 1023;
    const size_t base = ((size_t)b * H_HEAD * N_SEQ + n) * N_SEQ;
    const int m0 = tid * 4;
    const int lane = tid & 31, wid = tid >> 5;

    float t[12][4];
#pragma unroll
    for (int g = 0; g < 12; g++) {
        float bl = sbl[g];
        t[g][0] = bl; t[g][1] = bl; t[g][2] = bl; t[g][3] = bl;
    }
#pragma unroll
    for (int h = 0; h < 12; h++) {
        float4 s4 = *reinterpret_cast<const float4*>(g_scores + base + (size_t)h * N_SEQ * N_SEQ + m0);
#pragma unroll
        for (int g = 0; g < 12; g++) {
            float wl = swl[h * 12 + g];
            t[g][0] = fmaf(s4.x, wl, t[g][0]);
            t[g][1] = fmaf(s4.y, wl, t[g][1]);
            t[g][2] = fmaf(s4.z, wl, t[g][2]);
            t[g][3] = fmaf(s4.w, wl, t[g][3]);
        }
    }

    float lmax[12];
#pragma unroll
    for (int g = 0; g < 12; g++) {
        float v = fmaxf(fmaxf(t[g][0], t[g][1]), fmaxf(t[g][2], t[g][3]));
#pragma unroll
        for (int o = 16; o > 0; o >>= 1) v = fmaxf(v, __shfl_xor_sync(0xffffffffu, v, o));
        if (lane == 0) red[wid][g] = v;
    }
    __syncthreads();
#pragma unroll
    for (int g = 0; g < 12; g++) {
        float v = red[0][g];
#pragma unroll
        for (int w = 1; w < 8; w++) v = fmaxf(v, red[w][g]);
        lmax[g] = v;
    }
    __syncthreads();

    float lsum[12];
#pragma unroll
    for (int g = 0; g < 12; g++) {
        t[g][0] = __expf(t[g][0] - lmax[g]);
        t[g][1] = __expf(t[g][1] - lmax[g]);
        t[g][2] = __expf(t[g][2] - lmax[g]);
        t[g][3] = __expf(t[g][3] - lmax[g]);
        float v = (t[g][0] + t[g][1]) + (t[g][2] + t[g][3]);
#pragma unroll
        for (int o = 16; o > 0; o >>= 1) v += __shfl_xor_sync(0xffffffffu, v, o);
        if (lane == 0) red[wid][g] = v;
    }
    __syncthreads();
#pragma unroll
    for (int g = 0; g < 12; g++) {
        float v = red[0][g];
#pragma unroll
        for (int w = 1; w < 8; w++) v += red[w][g];
        lsum[g] = 1.0f / v;
    }

#pragma unroll
    for (int g = 0; g < 12; g++) {
        t[g][0] *= lsum[g]; t[g][1] *= lsum[g]; t[g][2] *= lsum[g]; t[g][3] *= lsum[g];
    }

#pragma unroll
    for (int g = 0; g < 12; g++) {
        float o0 = sbw[g], o1 = sbw[g], o2 = sbw[g], o3 = sbw[g];
#pragma unroll
        for (int h = 0; h < 12; h++) {
            float ww = sww[h * 12 + g];
            o0 = fmaf(t[h][0], ww, o0);
            o1 = fmaf(t[h][1], ww, o1);
            o2 = fmaf(t[h][2], ww, o2);
            o3 = fmaf(t[h][3], ww, o3);
        }
        *reinterpret_cast<float4*>(g_scores + base + (size_t)g * N_SEQ * N_SEQ + m0) =
            make_float4(o0, o1, o2, o3);
    }
}

// ---------------------------------------------------------------------------
extern "C" void kernel_launch(void* const* d_in, const int* in_sizes, int n_in,
                              void* d_out, int out_size)
{
    const float* x      = (const float*)d_in[0];
    const float* w_qkv  = (const float*)d_in[1];
    const float* b_qkv  = (const float*)d_in[2];
    const float* w_l    = (const float*)d_in[3];
    const float* b_l    = (const float*)d_in[4];
    const float* w_w    = (const float*)d_in[5];
    const float* b_w    = (const float*)d_in[6];
    const float* w_proj = (const float*)d_in[7];
    const float* b_proj = (const float*)d_in[8];
    float* out = (float*)d_out;

    float *qkv_p, *scores_p, *av_p, *vT_p, *wqkvT_p, *wprojT_p;
    cudaGetSymbolAddress((void**)&qkv_p, g_qkv);
    cudaGetSymbolAddress((void**)&scores_p, g_scores);
    cudaGetSymbolAddress((void**)&av_p, g_av);
    cudaGetSymbolAddress((void**)&vT_p, g_vT);
    cudaGetSymbolAddress((void**)&wqkvT_p, g_wqkvT);
    cudaGetSymbolAddress((void**)&wprojT_p, g_wprojT);

    // 0) weight transposes (cheap; also pre-round to tf32)
    transpose2d<<<dim3(QKV_LD / 32, C_DIM / 32), dim3(32, 8)>>>(w_qkv, wqkvT_p, C_DIM, QKV_LD);
    transpose2d<<<dim3(C_DIM / 32, C_DIM / 32), dim3(32, 8)>>>(w_proj, wprojT_p, C_DIM, C_DIM);

    const long long QB = (long long)N_SEQ * QKV_LD;      // per-b stride in g_qkv
    const long long SH = (long long)N_SEQ * N_SEQ;       // per-h stride in scores
    const long long VH = (long long)D_HEAD * N_SEQ;      // per-h stride in g_vT

    // 1) QKV projection: [8192,768] @ wqkvT[2304,768]^T + bias
    gemm_nt_tf32<128, false><<<dim3(QKV_LD / 128, B_SZ * N_SEQ / 128, 1), 256>>>(
        x, wqkvT_p, b_qkv, qkv_p, C_DIM, C_DIM, C_DIM, QKV_LD,
        0, 0, 0, 0, 0, 0, 1.0f);

    // 2) transpose V slices into g_vT[z][d][m] (tf32 pre-rounded)
    transpose_v<<<dim3(N_SEQ / 32, D_HEAD / 32, B_SZ * H_HEAD), dim3(32, 8)>>>();

    // 3) scores = SCALE * q @ k^T per (b,h)
    gemm_nt_tf32<128, true><<<dim3(N_SEQ / 128, N_SEQ / 128, B_SZ * H_HEAD), 256>>>(
        qkv_p, qkv_p + C_DIM, nullptr, scores_p, D_HEAD, QKV_LD, QKV_LD, N_SEQ,
        QB, D_HEAD, QB, D_HEAD, H_HEAD * SH, SH, SCALE);

    // 4) fused talking-heads pre-mix + softmax + post-mix (in place)
    mixsoftmax_kernel<<<B_SZ * N_SEQ, 256>>>(w_l, b_l, w_w, b_w);

    // 5) av = attn @ vT^T  -> g_av[b][n][h*64+d]
    gemm_nt_tf32<64, false><<<dim3(1, N_SEQ / 128, B_SZ * H_HEAD), 256>>>(
        scores_p, vT_p, nullptr, av_p, N_SEQ, N_SEQ, N_SEQ, C_DIM,
        H_HEAD * SH, SH, H_HEAD * VH, VH, (long long)N_SEQ * C_DIM, D_HEAD, 1.0f);

    // 6) out = av @ wprojT^T + bias
    gemm_nt_tf32<128, false><<<dim3(C_DIM / 128, B_SZ * N_SEQ / 128, 1), 256>>>(
        av_p, wprojT_p, b_proj, out, C_DIM, C_DIM, C_DIM, C_DIM,
        0, 0, 0, 0, 0, 0, 1.0f);
}

// round 6
// speedup vs baseline: 2.4669x; 1.0148x over previous
#include <cuda_runtime.h>
#include <math.h>

// Problem constants
#define B_SZ   8
#define N_SEQ  1024
#define C_DIM  768
#define H_HEAD 12
#define D_HEAD 64
#define QKV_LD 2304            // 3*C
#define SCALE  0.125f          // 64^-0.5

// Scratch (allocation-free: __device__ globals)
__device__ float g_qkv[(size_t)B_SZ * N_SEQ * 3 * C_DIM];          // [8192, 2304] (tf32-rounded)
__device__ float g_scores[(size_t)B_SZ * H_HEAD * N_SEQ * N_SEQ];  // [96, 1024, 1024]
__device__ float g_av[(size_t)B_SZ * N_SEQ * C_DIM];               // [8192, 768]  (tf32-rounded)
__device__ float g_vT[(size_t)B_SZ * H_HEAD * D_HEAD * N_SEQ];     // [96, 64, 1024] (tf32-rounded)
__device__ float g_wqkvT[(size_t)3 * C_DIM * C_DIM];               // [2304, 768]  (tf32-rounded)
__device__ float g_wprojT[(size_t)C_DIM * C_DIM];                  // [768, 768]   (tf32-rounded)

// ---------------------------------------------------------------------------
// helpers
// ---------------------------------------------------------------------------
__device__ __forceinline__ unsigned f2tf(float x) {
    unsigned u;
    asm("cvt.rna.tf32.f32 %0, %1;" : "=r"(u) : "f"(x));
    return u;
}

__device__ __forceinline__ void cpa16(unsigned s, const float* g) {
    asm volatile("cp.async.cg.shared.global [%0], [%1], 16;" :: "r"(s), "l"(g));
}
#define CPA_COMMIT() asm volatile("cp.async.commit_group;")
#define CPA_WAIT(n)  asm volatile("cp.async.wait_group %0;" :: "n"(n))

#define MMA_TF32(d, a, b)                                                     \
    asm volatile(                                                             \
        "mma.sync.aligned.m16n8k8.row.col.f32.tf32.tf32.f32 "                 \
        "{%0,%1,%2,%3}, {%4,%5,%6,%7}, {%8,%9}, {%0,%1,%2,%3};"               \
        : "+f"(d[0]), "+f"(d[1]), "+f"(d[2]), "+f"(d[3])                      \
        : "r"(a[0]), "r"(a[1]), "r"(a[2]), "r"(a[3]), "r"(b[0]), "r"(b[1]))

// ---------------------------------------------------------------------------
// Generic NT tf32 tensor GEMM: C[M,N] = scale * (A[M,K] @ B[N,K]^T) + bias[N]
// BM=128, BK=16, 256 threads (8 warps in 4x2), warp tile 32 x (BN/2),
// mma m16n8k8, 3-stage cp.async pipeline, dynamic smem.
// B operands are always pre-rounded to tf32 in gmem. A cvt'd at consume iff CVA.
// RND: round epilogue output to tf32 (for tensors consumed by later GEMMs).
// ---------------------------------------------------------------------------
template<int BN, bool CVA, bool RND>
__global__ __launch_bounds__(256) void gemm_nt_tf32(
    const float* __restrict__ Ag, const float* __restrict__ Bg,
    const float* __restrict__ bias, float* __restrict__ Cg,
    int K, int lda, int ldb, int ldc,
    long long az1, long long az2, long long bz1, long long bz2,
    long long cz1, long long cz2, float scale)
{
    constexpr int WN = BN / 2;    // warp N tile
    constexpr int NI = WN / 8;    // mma tiles along N per warp
    constexpr int BLD = BN / 64;  // B-tile float4 load rounds
    constexpr int A_STG = 128 * 20;
    constexpr int B_STG = BN * 20;

    extern __shared__ float smem[];
    float* As = smem;             // [3][128][20]
    float* Bs = smem + 3 * A_STG; // [3][BN][20]

    const int tid = threadIdx.x;
    const int lane = tid & 31, warp = tid >> 5;
    const int wm = warp & 3, wn = warp >> 2;
    const int g = lane >> 2, tg = lane & 3;

    const int z = blockIdx.z;
    const int zb = z / H_HEAD, zh = z % H_HEAD;
    const float* A = Ag + zb * az1 + zh * az2 + (size_t)blockIdx.y * 128 * lda;
    const float* B = Bg + zb * bz1 + zh * bz2 + (size_t)blockIdx.x * BN * ldb;
    float* C = Cg + zb * cz1 + zh * cz2;

    const int ar = tid >> 2;
    const int akc = (tid & 3) << 2;

    float acc[2][NI][4];
#pragma unroll
    for (int mi = 0; mi < 2; mi++)
#pragma unroll
        for (int ni = 0; ni < NI; ni++)
#pragma unroll
            for (int j = 0; j < 4; j++) acc[mi][ni][j] = 0.f;

    const int niter = K >> 4;

    auto stage_load = [&](int st, int k0) {
#pragma unroll
        for (int l = 0; l < 2; l++) {
            int r = ar + l * 64;
            unsigned sa = (unsigned)__cvta_generic_to_shared(As + st * A_STG + r * 20 + akc);
            cpa16(sa, A + (size_t)r * lda + k0 + akc);
        }
#pragma unroll
        for (int l = 0; l < BLD; l++) {
            int r = ar + l * 64;
            unsigned sb = (unsigned)__cvta_generic_to_shared(Bs + st * B_STG + r * 20 + akc);
            cpa16(sb, B + (size_t)r * ldb + k0 + akc);
        }
        CPA_COMMIT();
    };

    stage_load(0, 0);
    stage_load(1, 16);

    int st = 0;
    for (int i = 0; i < niter; i++) {
        // Tail fix: on the final iteration no new group was committed after
        // this stage's, so WAIT(1) would let the group feeding THIS stage
        // stay in flight. Drain fully instead.
        if (i + 1 < niter) { CPA_WAIT(1); } else { CPA_WAIT(0); }
        __syncthreads();
        int nld = i + 2;
        if (nld < niter) {
            int ls = nld - (nld / 3) * 3;
            stage_load(ls, nld << 4);
        }

        const float* Ab = As + st * A_STG;
        const float* Bb = Bs + st * B_STG;
#pragma unroll
        for (int kk = 0; kk < 16; kk += 8) {
            unsigned a[2][4], b[NI][2];
#pragma unroll
            for (int mi = 0; mi < 2; mi++) {
                int r = wm * 32 + mi * 16 + g;
                if (CVA) {
                    a[mi][0] = f2tf(Ab[r * 20 + kk + tg]);
                    a[mi][1] = f2tf(Ab[(r + 8) * 20 + kk + tg]);
                    a[mi][2] = f2tf(Ab[r * 20 + kk + 4 + tg]);
                    a[mi][3] = f2tf(Ab[(r + 8) * 20 + kk + 4 + tg]);
                } else {
                    a[mi][0] = __float_as_uint(Ab[r * 20 + kk + tg]);
                    a[mi][1] = __float_as_uint(Ab[(r + 8) * 20 + kk + tg]);
                    a[mi][2] = __float_as_uint(Ab[r * 20 + kk + 4 + tg]);
                    a[mi][3] = __float_as_uint(Ab[(r + 8) * 20 + kk + 4 + tg]);
                }
            }
#pragma unroll
            for (int ni = 0; ni < NI; ni++) {
                int n = wn * WN + ni * 8 + g;
                b[ni][0] = __float_as_uint(Bb[n * 20 + kk + tg]);
                b[ni][1] = __float_as_uint(Bb[n * 20 + kk + 4 + tg]);
            }
#pragma unroll
            for (int mi = 0; mi < 2; mi++)
#pragma unroll
                for (int ni = 0; ni < NI; ni++)
                    MMA_TF32(acc[mi][ni], a[mi], b[ni]);
        }
        st++; if (st == 3) st = 0;
    }

    // epilogue
    const int row_base = blockIdx.y * 128 + wm * 32;
    const int col_base = blockIdx.x * BN + wn * WN;
#pragma unroll
    for (int mi = 0; mi < 2; mi++) {
#pragma unroll
        for (int ni = 0; ni < NI; ni++) {
            int r0 = row_base + mi * 16 + g;
            int c = col_base + ni * 8 + 2 * tg;
            float b0 = 0.f, b1 = 0.f;
            if (bias) { b0 = bias[c]; b1 = bias[c + 1]; }
            float e00 = acc[mi][ni][0] * scale + b0;
            float e01 = acc[mi][ni][1] * scale + b1;
            float e10 = acc[mi][ni][2] * scale + b0;
            float e11 = acc[mi][ni][3] * scale + b1;
            if (RND) {
                e00 = __uint_as_float(f2tf(e00));
                e01 = __uint_as_float(f2tf(e01));
                e10 = __uint_as_float(f2tf(e10));
                e11 = __uint_as_float(f2tf(e11));
            }
            *reinterpret_cast<float2*>(C + (size_t)r0 * ldc + c) = make_float2(e00, e01);
            *reinterpret_cast<float2*>(C + (size_t)(r0 + 8) * ldc + c) = make_float2(e10, e11);
        }
    }
}

// ---------------------------------------------------------------------------
// 32x32 tiled transpose + tf32 pre-round: out[c][r] = tf32(in[r][c])
// ---------------------------------------------------------------------------
__global__ void transpose2d(const float* __restrict__ in, float* __restrict__ out,
                            int R, int Cc)
{
    __shared__ float t[32][33];
    int c0 = blockIdx.x * 32, r0 = blockIdx.y * 32;
    int x = threadIdx.x, y = threadIdx.y;
#pragma unroll
    for (int i = 0; i < 4; i++)
        t[y + i * 8][x] = in[(size_t)(r0 + y + i * 8) * Cc + c0 + x];
    __syncthreads();
#pragma unroll
    for (int i = 0; i < 4; i++)
        out[(size_t)(c0 + y + i * 8) * R + r0 + x] =
            __uint_as_float(f2tf(t[x][y + i * 8]));
}

// V slice of g_qkv -> g_vT[z][d][m], tf32 pre-rounded (idempotent re-round).
__global__ void transpose_v()
{
    __shared__ float t[32][33];
    int z = blockIdx.z;
    int b = z / H_HEAD, h = z % H_HEAD;
    const float* in = g_qkv + (size_t)b * N_SEQ * QKV_LD + 2 * C_DIM + h * D_HEAD;
    float* out = g_vT + (size_t)z * D_HEAD * N_SEQ;
    int m0 = blockIdx.x * 32, d0 = blockIdx.y * 32;
    int x = threadIdx.x, y = threadIdx.y;
#pragma unroll
    for (int i = 0; i < 4; i++)
        t[y + i * 8][x] = in[(size_t)(m0 + y + i * 8) * QKV_LD + d0 + x];
    __syncthreads();
#pragma unroll
    for (int i = 0; i < 4; i++)
        out[(size_t)(d0 + y + i * 8) * N_SEQ + m0 + x] =
            __uint_as_float(f2tf(t[x][y + i * 8]));
}

// ---------------------------------------------------------------------------
// Fused pre-mix (w_l) -> softmax over m -> post-mix (w_w), in-place on scores.
// Output written tf32-rounded (bit-identical to AV-side consume cvt).
// ---------------------------------------------------------------------------
__global__ __launch_bounds__(256) void mixsoftmax_kernel(
    const float* __restrict__ w_l, const float* __restrict__ b_l,
    const float* __restrict__ w_w, const float* __restrict__ b_w)
{
    __shared__ float swl[144], sww[144], sbl[12], sbw[12];
    __shared__ float red[8][12];
    const int tid = threadIdx.x;
    if (tid < 144) { swl[tid] = w_l[tid]; sww[tid] = w_w[tid]; }
    if (tid < 12)  { sbl[tid] = b_l[tid]; sbw[tid] = b_w[tid]; }
    __syncthreads();

    const int bn = blockIdx.x;
    const int b = bn >> 10, n = bn & 1023;
    const size_t base = ((size_t)b * H_HEAD * N_SEQ + n) * N_SEQ;
    const int m0 = tid * 4;
    const int lane = tid & 31, wid = tid >> 5;

    float t[12][4];
#pragma unroll
    for (int g = 0; g < 12; g++) {
        float bl = sbl[g];
        t[g][0] = bl; t[g][1] = bl; t[g][2] = bl; t[g][3] = bl;
    }
#pragma unroll
    for (int h = 0; h < 12; h++) {
        float4 s4 = *reinterpret_cast<const float4*>(g_scores + base + (size_t)h * N_SEQ * N_SEQ + m0);
#pragma unroll
        for (int g = 0; g < 12; g++) {
            float wl = swl[h * 12 + g];
            t[g][0] = fmaf(s4.x, wl, t[g][0]);
            t[g][1] = fmaf(s4.y, wl, t[g][1]);
            t[g][2] = fmaf(s4.z, wl, t[g][2]);
            t[g][3] = fmaf(s4.w, wl, t[g][3]);
        }
    }

    float lmax[12];
#pragma unroll
    for (int g = 0; g < 12; g++) {
        float v = fmaxf(fmaxf(t[g][0], t[g][1]), fmaxf(t[g][2], t[g][3]));
#pragma unroll
        for (int o = 16; o > 0; o >>= 1) v = fmaxf(v, __shfl_xor_sync(0xffffffffu, v, o));
        if (lane == 0) red[wid][g] = v;
    }
    __syncthreads();
#pragma unroll
    for (int g = 0; g < 12; g++) {
        float v = red[0][g];
#pragma unroll
        for (int w = 1; w < 8; w++) v = fmaxf(v, red[w][g]);
        lmax[g] = v;
    }
    __syncthreads();

    float lsum[12];
#pragma unroll
    for (int g = 0; g < 12; g++) {
        t[g][0] = __expf(t[g][0] - lmax[g]);
        t[g][1] = __expf(t[g][1] - lmax[g]);
        t[g][2] = __expf(t[g][2] - lmax[g]);
        t[g][3] = __expf(t[g][3] - lmax[g]);
        float v = (t[g][0] + t[g][1]) + (t[g][2] + t[g][3]);
#pragma unroll
        for (int o = 16; o > 0; o >>= 1) v += __shfl_xor_sync(0xffffffffu, v, o);
        if (lane == 0) red[wid][g] = v;
    }
    __syncthreads();
#pragma unroll
    for (int g = 0; g < 12; g++) {
        float v = red[0][g];
#pragma unroll
        for (int w = 1; w < 8; w++) v += red[w][g];
        lsum[g] = 1.0f / v;
    }

#pragma unroll
    for (int g = 0; g < 12; g++) {
        t[g][0] *= lsum[g]; t[g][1] *= lsum[g]; t[g][2] *= lsum[g]; t[g][3] *= lsum[g];
    }

#pragma unroll
    for (int g = 0; g < 12; g++) {
        float o0 = sbw[g], o1 = sbw[g], o2 = sbw[g], o3 = sbw[g];
#pragma unroll
        for (int h = 0; h < 12; h++) {
            float ww = sww[h * 12 + g];
            o0 = fmaf(t[h][0], ww, o0);
            o1 = fmaf(t[h][1], ww, o1);
            o2 = fmaf(t[h][2], ww, o2);
            o3 = fmaf(t[h][3], ww, o3);
        }
        *reinterpret_cast<float4*>(g_scores + base + (size_t)g * N_SEQ * N_SEQ + m0) =
            make_float4(__uint_as_float(f2tf(o0)), __uint_as_float(f2tf(o1)),
                        __uint_as_float(f2tf(o2)), __uint_as_float(f2tf(o3)));
    }
}

// ---------------------------------------------------------------------------
extern "C" void kernel_launch(void* const* d_in, const int* in_sizes, int n_in,
                              void* d_out, int out_size)
{
    const float* x      = (const float*)d_in[0];
    const float* w_qkv  = (const float*)d_in[1];
    const float* b_qkv  = (const float*)d_in[2];
    const float* w_l    = (const float*)d_in[3];
    const float* b_l    = (const float*)d_in[4];
    const float* w_w    = (const float*)d_in[5];
    const float* b_w    = (const float*)d_in[6];
    const float* w_proj = (const float*)d_in[7];
    const float* b_proj = (const float*)d_in[8];
    float* out = (float*)d_out;

    float *qkv_p, *scores_p, *av_p, *vT_p, *wqkvT_p, *wprojT_p;
    cudaGetSymbolAddress((void**)&qkv_p, g_qkv);
    cudaGetSymbolAddress((void**)&scores_p, g_scores);
    cudaGetSymbolAddress((void**)&av_p, g_av);
    cudaGetSymbolAddress((void**)&vT_p, g_vT);
    cudaGetSymbolAddress((void**)&wqkvT_p, g_wqkvT);
    cudaGetSymbolAddress((void**)&wprojT_p, g_wprojT);

    // dynamic smem opt-in (3 stages)
    const int smem128 = 3 * (128 + 128) * 20 * 4;   // 61440
    const int smem64  = 3 * (128 + 64) * 20 * 4;    // 46080
    cudaFuncSetAttribute(gemm_nt_tf32<128, true,  true >, cudaFuncAttributeMaxDynamicSharedMemorySize, smem128);
    cudaFuncSetAttribute(gemm_nt_tf32<128, false, false>, cudaFuncAttributeMaxDynamicSharedMemorySize, smem128);
    cudaFuncSetAttribute(gemm_nt_tf32<64,  false, true >, cudaFuncAttributeMaxDynamicSharedMemorySize, smem64);

    // 0) weight transposes (tf32 pre-rounded)
    transpose2d<<<dim3(QKV_LD / 32, C_DIM / 32), dim3(32, 8)>>>(w_qkv, wqkvT_p, C_DIM, QKV_LD);
    transpose2d<<<dim3(C_DIM / 32, C_DIM / 32), dim3(32, 8)>>>(w_proj, wprojT_p, C_DIM, C_DIM);

    const long long QB = (long long)N_SEQ * QKV_LD;
    const long long SH = (long long)N_SEQ * N_SEQ;
    const long long VH = (long long)D_HEAD * N_SEQ;

    // 1) QKV projection (A = x needs consume cvt; output tf32-rounded)
    gemm_nt_tf32<128, true, true><<<dim3(QKV_LD / 128, B_SZ * N_SEQ / 128, 1), 256, smem128>>>(
        x, wqkvT_p, b_qkv, qkv_p, C_DIM, C_DIM, C_DIM, QKV_LD,
        0, 0, 0, 0, 0, 0, 1.0f);

    // 2) transpose V slices into g_vT[z][d][m]
    transpose_v<<<dim3(N_SEQ / 32, D_HEAD / 32, B_SZ * H_HEAD), dim3(32, 8)>>>();

    // 3) scores = SCALE * q @ k^T per (b,h) (both operands pre-rounded; raw fp32 out)
    gemm_nt_tf32<128, false, false><<<dim3(N_SEQ / 128, N_SEQ / 128, B_SZ * H_HEAD), 256, smem128>>>(
        qkv_p, qkv_p + C_DIM, nullptr, scores_p, D_HEAD, QKV_LD, QKV_LD, N_SEQ,
        QB, D_HEAD, QB, D_HEAD, H_HEAD * SH, SH, SCALE);

    // 4) fused talking-heads pre-mix + softmax + post-mix (in place, tf32-rounded out)
    mixsoftmax_kernel<<<B_SZ * N_SEQ, 256>>>(w_l, b_l, w_w, b_w);

    // 5) av = attn @ vT^T (both pre-rounded; output tf32-rounded)
    gemm_nt_tf32<64, false, true><<<dim3(1, N_SEQ / 128, B_SZ * H_HEAD), 256, smem64>>>(
        scores_p, vT_p, nullptr, av_p, N_SEQ, N_SEQ, N_SEQ, C_DIM,
        H_HEAD * SH, SH, H_HEAD * VH, VH, (long long)N_SEQ * C_DIM, D_HEAD, 1.0f);

    // 6) out = av @ wprojT^T + bias (final: no rounding)
    gemm_nt_tf32<128, false, false><<<dim3(C_DIM / 128, B_SZ * N_SEQ / 128, 1), 256, smem128>>>(
        av_p, wprojT_p, b_proj, out, C_DIM, C_DIM, C_DIM, C_DIM,
        0, 0, 0, 0, 0, 0, 1.0f);
}

// round 8
// speedup vs baseline: 3.6831x; 1.4930x over previous
#include <cuda_runtime.h>
#include <cuda_fp16.h>
#include <math.h>
#include <stdint.h>

// Problem constants
#define B_SZ   8
#define N_SEQ  1024
#define C_DIM  768
#define H_HEAD 12
#define D_HEAD 64
#define QKV_LD 2304            // 3*C
#define SCALE  0.125f          // 64^-0.5

// Scratch (allocation-free: __device__ globals). All GEMM operands are fp16
// (11-bit significand == tf32's), accumulations fp32, raw scores fp32.
__device__ __half g_xh[(size_t)B_SZ * N_SEQ * C_DIM];
__device__ __half g_qkv[(size_t)B_SZ * N_SEQ * 3 * C_DIM];           // [8192, 2304]
__device__ float  g_scores[(size_t)B_SZ * H_HEAD * N_SEQ * N_SEQ];   // [96, 1024, 1024] fp32
__device__ __half g_attn[(size_t)B_SZ * H_HEAD * N_SEQ * N_SEQ];     // [96, 1024, 1024]
__device__ __half g_av[(size_t)B_SZ * N_SEQ * C_DIM];                // [8192, 768]
__device__ __half g_vT[(size_t)B_SZ * H_HEAD * D_HEAD * N_SEQ];      // [96, 64, 1024]
__device__ __half g_wqkvT[(size_t)3 * C_DIM * C_DIM];                // [2304, 768]
__device__ __half g_wprojT[(size_t)C_DIM * C_DIM];                   // [768, 768]

// ---------------------------------------------------------------------------
// helpers
// ---------------------------------------------------------------------------
__device__ __forceinline__ void cpa16(unsigned s, const void* g) {
    asm volatile("cp.async.cg.shared.global [%0], [%1], 16;" :: "r"(s), "l"(g));
}
#define CPA_COMMIT() asm volatile("cp.async.commit_group;")
#define CPA_WAIT(n)  asm volatile("cp.async.wait_group %0;" :: "n"(n))

__device__ __forceinline__ uint32_t pack_h2(float a, float b) {
    __half2 h = __floats2half2_rn(a, b);
    return *reinterpret_cast<uint32_t*>(&h);
}

#define MMA_F16(d, a, b)                                                      \
    asm volatile(                                                             \
        "mma.sync.aligned.m16n8k16.row.col.f32.f16.f16.f32 "                  \
        "{%0,%1,%2,%3}, {%4,%5,%6,%7}, {%8,%9}, {%0,%1,%2,%3};"               \
        : "+f"(d[0]), "+f"(d[1]), "+f"(d[2]), "+f"(d[3])                      \
        : "r"(a[0]), "r"(a[1]), "r"(a[2]), "r"(a[3]), "r"(b[0]), "r"(b[1]))

// ---------------------------------------------------------------------------
// fp16 NT GEMM: C[M,N] = scale * (A[M,K] @ B[N,K]^T) + bias[N]
// BM=128, BK=32, 256 threads (8 warps 4x2), warp tile 32 x (BN/2),
// mma m16n8k16 (fp16 in, fp32 acc), 3-stage cp.async pipeline.
// smem rows padded to 40 halves (conflict-free for fragment LDS).
// OUT_HALF: store C as __half (rn round == old tf32 round); else fp32.
// ---------------------------------------------------------------------------
template<int BN, bool OUT_HALF>
__global__ __launch_bounds__(256) void gemm_f16(
    const __half* __restrict__ Ag, const __half* __restrict__ Bg,
    const float* __restrict__ bias, void* __restrict__ Cg,
    int K, int lda, int ldb, int ldc,
    long long az1, long long az2, long long bz1, long long bz2,
    long long cz1, long long cz2, float scale)
{
    constexpr int WN = BN / 2;
    constexpr int NI = WN / 8;
    constexpr int ASTG = 128 * 40;        // halves per A stage
    constexpr int BSTG = BN * 40;

    extern __shared__ __half sh[];
    __half* As = sh;                      // [3][128][40]
    __half* Bs = sh + 3 * ASTG;           // [3][BN][40]
    const uint32_t sb = (uint32_t)__cvta_generic_to_shared(sh);
    const uint32_t sbB = sb + 3 * ASTG * 2;

    const int tid = threadIdx.x;
    const int lane = tid & 31, warp = tid >> 5;
    const int wm = warp & 3, wn = warp >> 2;
    const int g = lane >> 2, tg = lane & 3;

    const int z = blockIdx.z;
    const int zb = z / H_HEAD, zh = z % H_HEAD;
    const __half* A = Ag + zb * az1 + zh * az2 + (size_t)blockIdx.y * 128 * lda;
    const __half* B = Bg + zb * bz1 + zh * bz2 + (size_t)blockIdx.x * BN * ldb;

    const int lr = tid >> 2;              // chunk row
    const int lc = (tid & 3) << 3;        // chunk col (halves)

    float acc[2][NI][4];
#pragma unroll
    for (int mi = 0; mi < 2; mi++)
#pragma unroll
        for (int ni = 0; ni < NI; ni++)
#pragma unroll
            for (int j = 0; j < 4; j++) acc[mi][ni][j] = 0.f;

    const int niter = K >> 5;

    auto stage_load = [&](int st, int k0) {
#pragma unroll
        for (int l = 0; l < 2; l++) {
            int r = lr + l * 64;
            cpa16(sb + (st * ASTG + r * 40 + lc) * 2, A + (size_t)r * lda + k0 + lc);
        }
#pragma unroll
        for (int l = 0; l < BN / 64; l++) {
            int r = lr + l * 64;
            cpa16(sbB + (st * BSTG + r * 40 + lc) * 2, B + (size_t)r * ldb + k0 + lc);
        }
        CPA_COMMIT();
    };

    stage_load(0, 0);
    if (niter > 1) stage_load(1, 32);

    int st = 0;
    for (int i = 0; i < niter; i++) {
        if (i + 1 < niter) { CPA_WAIT(1); } else { CPA_WAIT(0); }
        __syncthreads();
        int nld = i + 2;
        if (nld < niter) {
            int ls = nld - (nld / 3) * 3;
            stage_load(ls, nld << 5);
        }

        const __half* Ab = As + st * ASTG;
        const __half* Bb = Bs + st * BSTG;
#pragma unroll
        for (int kk = 0; kk < 32; kk += 16) {
            unsigned a[2][4], b[NI][2];
#pragma unroll
            for (int mi = 0; mi < 2; mi++) {
                int r = wm * 32 + mi * 16 + g;
                a[mi][0] = *reinterpret_cast<const uint32_t*>(Ab + r * 40 + kk + 2 * tg);
                a[mi][1] = *reinterpret_cast<const uint32_t*>(Ab + (r + 8) * 40 + kk + 2 * tg);
                a[mi][2] = *reinterpret_cast<const uint32_t*>(Ab + r * 40 + kk + 8 + 2 * tg);
                a[mi][3] = *reinterpret_cast<const uint32_t*>(Ab + (r + 8) * 40 + kk + 8 + 2 * tg);
            }
#pragma unroll
            for (int ni = 0; ni < NI; ni++) {
                int n = wn * WN + ni * 8 + g;
                b[ni][0] = *reinterpret_cast<const uint32_t*>(Bb + n * 40 + kk + 2 * tg);
                b[ni][1] = *reinterpret_cast<const uint32_t*>(Bb + n * 40 + kk + 8 + 2 * tg);
            }
#pragma unroll
            for (int mi = 0; mi < 2; mi++)
#pragma unroll
                for (int ni = 0; ni < NI; ni++)
                    MMA_F16(acc[mi][ni], a[mi], b[ni]);
        }
        st++; if (st == 3) st = 0;
    }

    // epilogue
    const int row_base = blockIdx.y * 128 + wm * 32;
    const int col_base = blockIdx.x * BN + wn * WN;
#pragma unroll
    for (int mi = 0; mi < 2; mi++) {
#pragma unroll
        for (int ni = 0; ni < NI; ni++) {
            int r0 = row_base + mi * 16 + g;
            int c = col_base + ni * 8 + 2 * tg;
            float b0 = 0.f, b1 = 0.f;
            if (bias) { b0 = bias[c]; b1 = bias[c + 1]; }
            float e00 = acc[mi][ni][0] * scale + b0;
            float e01 = acc[mi][ni][1] * scale + b1;
            float e10 = acc[mi][ni][2] * scale + b0;
            float e11 = acc[mi][ni][3] * scale + b1;
            if (OUT_HALF) {
                __half* C = (__half*)Cg + zb * cz1 + zh * cz2;
                *reinterpret_cast<uint32_t*>(C + (size_t)r0 * ldc + c) = pack_h2(e00, e01);
                *reinterpret_cast<uint32_t*>(C + (size_t)(r0 + 8) * ldc + c) = pack_h2(e10, e11);
            } else {
                float* C = (float*)Cg + zb * cz1 + zh * cz2;
                *reinterpret_cast<float2*>(C + (size_t)r0 * ldc + c) = make_float2(e00, e01);
                *reinterpret_cast<float2*>(C + (size_t)(r0 + 8) * ldc + c) = make_float2(e10, e11);
            }
        }
    }
}

// ---------------------------------------------------------------------------
// elementwise fp16 round of x
// ---------------------------------------------------------------------------
__global__ void round_x_f16(const float* __restrict__ in, __half* __restrict__ out)
{
    int i = blockIdx.x * 256 + threadIdx.x;
    float4 v = reinterpret_cast<const float4*>(in)[i];
    uint2 p;
    p.x = pack_h2(v.x, v.y);
    p.y = pack_h2(v.z, v.w);
    reinterpret_cast<uint2*>(out)[i] = p;
}

// ---------------------------------------------------------------------------
// 32x32 tiled transpose fp32 -> fp16: out[c][r] = h(in[r][c])
// ---------------------------------------------------------------------------
__global__ void transpose2d(const float* __restrict__ in, __half* __restrict__ out,
                            int R, int Cc)
{
    __shared__ float t[32][33];
    int c0 = blockIdx.x * 32, r0 = blockIdx.y * 32;
    int x = threadIdx.x, y = threadIdx.y;
#pragma unroll
    for (int i = 0; i < 4; i++)
        t[y + i * 8][x] = in[(size_t)(r0 + y + i * 8) * Cc + c0 + x];
    __syncthreads();
#pragma unroll
    for (int i = 0; i < 4; i++)
        out[(size_t)(c0 + y + i * 8) * R + r0 + x] = __float2half_rn(t[x][y + i * 8]);
}

// V slice of g_qkv (half) -> g_vT[z][d][m] (half)
__global__ void transpose_v()
{
    __shared__ float t[32][33];
    int z = blockIdx.z;
    int b = z / H_HEAD, h = z % H_HEAD;
    const __half* in = g_qkv + (size_t)b * N_SEQ * QKV_LD + 2 * C_DIM + h * D_HEAD;
    __half* out = g_vT + (size_t)z * D_HEAD * N_SEQ;
    int m0 = blockIdx.x * 32, d0 = blockIdx.y * 32;
    int x = threadIdx.x, y = threadIdx.y;
#pragma unroll
    for (int i = 0; i < 4; i++)
        t[y + i * 8][x] = __half2float(in[(size_t)(m0 + y + i * 8) * QKV_LD + d0 + x]);
    __syncthreads();
#pragma unroll
    for (int i = 0; i < 4; i++)
        out[(size_t)(d0 + y + i * 8) * N_SEQ + m0 + x] = __float2half_rn(t[x][y + i * 8]);
}

// ---------------------------------------------------------------------------
// Fused pre-mix (w_l) -> softmax over m -> post-mix (w_w).
// Reads raw fp32 scores; writes post-mixed attn as fp16 into g_attn.
// ---------------------------------------------------------------------------
__global__ __launch_bounds__(256) void mixsoftmax_kernel(
    const float* __restrict__ w_l, const float* __restrict__ b_l,
    const float* __restrict__ w_w, const float* __restrict__ b_w)
{
    __shared__ float swl[144], sww[144], sbl[12], sbw[12];
    __shared__ float red[8][12];
    const int tid = threadIdx.x;
    if (tid < 144) { swl[tid] = w_l[tid]; sww[tid] = w_w[tid]; }
    if (tid < 12)  { sbl[tid] = b_l[tid]; sbw[tid] = b_w[tid]; }
    __syncthreads();

    const int bn = blockIdx.x;
    const int b = bn >> 10, n = bn & 1023;
    const size_t base = ((size_t)b * H_HEAD * N_SEQ + n) * N_SEQ;
    const int m0 = tid * 4;
    const int lane = tid & 31, wid = tid >> 5;

    float t[12][4];
#pragma unroll
    for (int g = 0; g < 12; g++) {
        float bl = sbl[g];
        t[g][0] = bl; t[g][1] = bl; t[g][2] = bl; t[g][3] = bl;
    }
#pragma unroll
    for (int h = 0; h < 12; h++) {
        float4 s4 = *reinterpret_cast<const float4*>(g_scores + base + (size_t)h * N_SEQ * N_SEQ + m0);
#pragma unroll
        for (int g = 0; g < 12; g++) {
            float wl = swl[h * 12 + g];
            t[g][0] = fmaf(s4.x, wl, t[g][0]);
            t[g][1] = fmaf(s4.y, wl, t[g][1]);
            t[g][2] = fmaf(s4.z, wl, t[g][2]);
            t[g][3] = fmaf(s4.w, wl, t[g][3]);
        }
    }

    float lmax[12];
#pragma unroll
    for (int g = 0; g < 12; g++) {
        float v = fmaxf(fmaxf(t[g][0], t[g][1]), fmaxf(t[g][2], t[g][3]));
#pragma unroll
        for (int o = 16; o > 0; o >>= 1) v = fmaxf(v, __shfl_xor_sync(0xffffffffu, v, o));
        if (lane == 0) red[wid][g] = v;
    }
    __syncthreads();
#pragma unroll
    for (int g = 0; g < 12; g++) {
        float v = red[0][g];
#pragma unroll
        for (int w = 1; w < 8; w++) v = fmaxf(v, red[w][g]);
        lmax[g] = v;
    }
    __syncthreads();

    float lsum[12];
#pragma unroll
    for (int g = 0; g < 12; g++) {
        t[g][0] = __expf(t[g][0] - lmax[g]);
        t[g][1] = __expf(t[g][1] - lmax[g]);
        t[g][2] = __expf(t[g][2] - lmax[g]);
        t[g][3] = __expf(t[g][3] - lmax[g]);
        float v = (t[g][0] + t[g][1]) + (t[g][2] + t[g][3]);
#pragma unroll
        for (int o = 16; o > 0; o >>= 1) v += __shfl_xor_sync(0xffffffffu, v, o);
        if (lane == 0) red[wid][g] = v;
    }
    __syncthreads();
#pragma unroll
    for (int g = 0; g < 12; g++) {
        float v = red[0][g];
#pragma unroll
        for (int w = 1; w < 8; w++) v += red[w][g];
        lsum[g] = 1.0f / v;
    }

#pragma unroll
    for (int g = 0; g < 12; g++) {
        t[g][0] *= lsum[g]; t[g][1] *= lsum[g]; t[g][2] *= lsum[g]; t[g][3] *= lsum[g];
    }

#pragma unroll
    for (int g = 0; g < 12; g++) {
        float o0 = sbw[g], o1 = sbw[g], o2 = sbw[g], o3 = sbw[g];
#pragma unroll
        for (int h = 0; h < 12; h++) {
            float ww = sww[h * 12 + g];
            o0 = fmaf(t[h][0], ww, o0);
            o1 = fmaf(t[h][1], ww, o1);
            o2 = fmaf(t[h][2], ww, o2);
            o3 = fmaf(t[h][3], ww, o3);
        }
        uint2 p;
        p.x = pack_h2(o0, o1);
        p.y = pack_h2(o2, o3);
        *reinterpret_cast<uint2*>(g_attn + base + (size_t)g * N_SEQ * N_SEQ + m0) = p;
    }
}

// ---------------------------------------------------------------------------
extern "C" void kernel_launch(void* const* d_in, const int* in_sizes, int n_in,
                              void* d_out, int out_size)
{
    const float* x      = (const float*)d_in[0];
    const float* w_qkv  = (const float*)d_in[1];
    const float* b_qkv  = (const float*)d_in[2];
    const float* w_l    = (const float*)d_in[3];
    const float* b_l    = (const float*)d_in[4];
    const float* w_w    = (const float*)d_in[5];
    const float* b_w    = (const float*)d_in[6];
    const float* w_proj = (const float*)d_in[7];
    const float* b_proj = (const float*)d_in[8];
    float* out = (float*)d_out;

    __half *xh_p, *qkv_p, *attn_p, *av_p, *vT_p, *wqkvT_p, *wprojT_p;
    float *scores_p;
    cudaGetSymbolAddress((void**)&xh_p, g_xh);
    cudaGetSymbolAddress((void**)&qkv_p, g_qkv);
    cudaGetSymbolAddress((void**)&scores_p, g_scores);
    cudaGetSymbolAddress((void**)&attn_p, g_attn);
    cudaGetSymbolAddress((void**)&av_p, g_av);
    cudaGetSymbolAddress((void**)&vT_p, g_vT);
    cudaGetSymbolAddress((void**)&wqkvT_p, g_wqkvT);
    cudaGetSymbolAddress((void**)&wprojT_p, g_wprojT);

    // dynamic smem: 3 stages * (128 + BN) rows * 40 halves * 2 bytes
    const int smem128 = 3 * (128 + 128) * 40 * 2;   // 61440
    const int smem64  = 3 * (128 + 64) * 40 * 2;    // 46080
    cudaFuncSetAttribute(gemm_f16<128, true >, cudaFuncAttributeMaxDynamicSharedMemorySize, smem128);
    cudaFuncSetAttribute(gemm_f16<128, false>, cudaFuncAttributeMaxDynamicSharedMemorySize, smem128);
    cudaFuncSetAttribute(gemm_f16<64,  true >, cudaFuncAttributeMaxDynamicSharedMemorySize, smem64);

    // 0) fp16 conversions: x, transposed weights
    round_x_f16<<<(B_SZ * N_SEQ * C_DIM / 4) / 256, 256>>>(x, xh_p);
    transpose2d<<<dim3(QKV_LD / 32, C_DIM / 32), dim3(32, 8)>>>(w_qkv, wqkvT_p, C_DIM, QKV_LD);
    transpose2d<<<dim3(C_DIM / 32, C_DIM / 32), dim3(32, 8)>>>(w_proj, wprojT_p, C_DIM, C_DIM);

    const long long QB = (long long)N_SEQ * QKV_LD;
    const long long SH = (long long)N_SEQ * N_SEQ;
    const long long VH = (long long)D_HEAD * N_SEQ;

    // 1) QKV projection: [8192,768] @ wqkvT^T + bias -> fp16 qkv
    gemm_f16<128, true><<<dim3(QKV_LD / 128, B_SZ * N_SEQ / 128, 1), 256, smem128>>>(
        xh_p, wqkvT_p, b_qkv, qkv_p, C_DIM, C_DIM, C_DIM, QKV_LD,
        0, 0, 0, 0, 0, 0, 1.0f);

    // 2) transpose V slices into g_vT[z][d][m]
    transpose_v<<<dim3(N_SEQ / 32, D_HEAD / 32, B_SZ * H_HEAD), dim3(32, 8)>>>();

    // 3) scores = SCALE * q @ k^T per (b,h) -> raw fp32
    gemm_f16<128, false><<<dim3(N_SEQ / 128, N_SEQ / 128, B_SZ * H_HEAD), 256, smem128>>>(
        qkv_p, qkv_p + C_DIM, nullptr, scores_p, D_HEAD, QKV_LD, QKV_LD, N_SEQ,
        QB, D_HEAD, QB, D_HEAD, H_HEAD * SH, SH, SCALE);

    // 4) fused talking-heads pre-mix + softmax + post-mix -> fp16 attn
    mixsoftmax_kernel<<<B_SZ * N_SEQ, 256>>>(w_l, b_l, w_w, b_w);

    // 5) av = attn @ vT^T -> fp16 av
    gemm_f16<64, true><<<dim3(1, N_SEQ / 128, B_SZ * H_HEAD), 256, smem64>>>(
        attn_p, vT_p, nullptr, av_p, N_SEQ, N_SEQ, N_SEQ, C_DIM,
        H_HEAD * SH, SH, H_HEAD * VH, VH, (long long)N_SEQ * C_DIM, D_HEAD, 1.0f);

    // 6) out = av @ wprojT^T + bias (fp32 out)
    gemm_f16<128, false><<<dim3(C_DIM / 128, B_SZ * N_SEQ / 128, 1), 256, smem128>>>(
        av_p, wprojT_p, b_proj, out, C_DIM, C_DIM, C_DIM, C_DIM,
        0, 0, 0, 0, 0, 0, 1.0f);
}